// round 11
// baseline (speedup 1.0000x reference)
#include <cuda_runtime.h>
#include <cuda_bf16.h>
#include <stdint.h>

// Problem constants
#define BATCH   1024
#define NFEAT   256
#define NSAMP   100000
// Tiling
#define BTILE   256                     // batch rows per CTA
#define NTHREADS 512                    // 16 warps = 8 (M) x 2 (N), each m32 x n32
#define FSUB    64                      // feature rows per subtile
#define NSUB64  1563                    // ceil(100000/64)
#define FEATPAD (NSUB64 * FSUB)         // 100032 rows (pad rows zeroed)
#define FGROUPS 37                      // 37 * 4 = 148 CTAs = one wave
#define BCHUNKS (BATCH / BTILE)         // 4
#define NCTAS   (FGROUPS * BCHUNKS)     // 148
#define NPART   (FGROUPS * 2)           // 74 partials per batch row (2 N-warps)

#define ASTRIDE 264                     // halves per smem row (+8 pad -> conflict-free ldmatrix)
#define A_BYTES (BTILE * ASTRIDE * 2)   // 135168
#define B_BYTES (FSUB * ASTRIDE * 2)    // 33792
#define SMEM_BYTES (A_BYTES + 2 * B_BYTES)  // 202752 (< 227KB)

#define CSCALE 28.853900817779268f      // (1/0.05) * log2(e): folded into bf16 A
#define LN2F   0.6931471805599453f
#define FIXM   150.0f                   // fixed softmax max (base-2); max logit ~123
#define C1CONST (12582912.0f - 150.0f)  // magic(1.5*2^23) - FIXM

__device__ float g_part[NPART * BATCH];
__device__ float g_tgt[BATCH];
__device__ int   g_sem = 0;
// bf16 feature bank, written once per run by cvt_kernel (pad rows zero)
__device__ __nv_bfloat16 g_featbf[(size_t)FEATPAD * NFEAT];

// 2^(v-150) on the FFMA pipe; clamp v>=24 => exponent >= -126.
__device__ __forceinline__ float exp2m150(float v) {
    v = fmaxf(v, 24.0f);
    float tj = v + C1CONST;
    float fi = tj - C1CONST;
    float f  = v - fi;
    float p  = 0.0096181291f;
    p = fmaf(p, f, 0.0555041087f);
    p = fmaf(p, f, 0.2402265070f);
    p = fmaf(p, f, 0.6931471806f);
    p = fmaf(p, f, 1.0f);
    return __int_as_float(__float_as_int(p) + (__float_as_int(tj) << 23));
}

__device__ __forceinline__ uint2 cvt2bf16(float4 v) {
    __nv_bfloat162 p0, p1;
    p0.x = __float2bfloat16_rn(v.x); p0.y = __float2bfloat16_rn(v.y);
    p1.x = __float2bfloat16_rn(v.z); p1.y = __float2bfloat16_rn(v.w);
    uint2 u;
    u.x = *(uint32_t*)&p0; u.y = *(uint32_t*)&p1;
    return u;
}

__device__ __forceinline__ void ldsm4(uint32_t& r0, uint32_t& r1, uint32_t& r2, uint32_t& r3,
                                      uint32_t addr) {
    asm volatile("ldmatrix.sync.aligned.m8n8.x4.shared.b16 {%0,%1,%2,%3}, [%4];"
                 : "=r"(r0), "=r"(r1), "=r"(r2), "=r"(r3) : "r"(addr));
}

__device__ __forceinline__ void mma16816(float* d, const uint32_t* a, const uint32_t* b) {
    asm volatile("mma.sync.aligned.m16n8k16.row.col.f32.bf16.bf16.f32 "
                 "{%0,%1,%2,%3}, {%4,%5,%6,%7}, {%8,%9}, {%0,%1,%2,%3};"
                 : "+f"(d[0]), "+f"(d[1]), "+f"(d[2]), "+f"(d[3])
                 : "r"(a[0]), "r"(a[1]), "r"(a[2]), "r"(a[3]), "r"(b[0]), "r"(b[1]));
}

__device__ __forceinline__ void cpasync16(uint32_t dst, const void* src) {
    asm volatile("cp.async.cg.shared.global [%0], [%1], 16;" :: "r"(dst), "l"(src) : "memory");
}
#define CP_COMMIT() asm volatile("cp.async.commit_group;" ::: "memory")
#define CP_WAIT0()  asm volatile("cp.async.wait_group 0;" ::: "memory")

// ---------------------------------------------------------------------------
// Pre-pass: fp32 features -> bf16 bank (pad rows zeroed). Pure streaming.
// ---------------------------------------------------------------------------
__global__ void __launch_bounds__(256)
cvt_kernel(const float* __restrict__ features)
{
    size_t i = (size_t)blockIdx.x * blockDim.x + threadIdx.x;
    const size_t stride = (size_t)gridDim.x * blockDim.x;
    const size_t n_real = (size_t)NSAMP * NFEAT / 4;     // 6,400,000 float4
    const size_t n_tot  = (size_t)FEATPAD * NFEAT / 4;   // 6,402,048
    const float4* src = (const float4*)features;
    uint2* dst = (uint2*)g_featbf;
    for (; i < n_tot; i += stride) {
        float4 v = (i < n_real) ? src[i] : make_float4(0.f, 0.f, 0.f, 0.f);
        dst[i] = cvt2bf16(v);
    }
}

// ---------------------------------------------------------------------------
// Fused main: target dots + GEMM (256x64 tiles, 8x2 warps m32n32, cp.async B)
// + fixed-M softmax sums + last-CTA merge.
// ---------------------------------------------------------------------------
__global__ void __launch_bounds__(NTHREADS, 1)
ce_fused(const float* __restrict__ inputs, const float* __restrict__ features,
         const int* __restrict__ t32, float* __restrict__ out)
{
    extern __shared__ char smem[];
    const int tid  = threadIdx.x;
    const int lane = tid & 31;
    const int wid  = tid >> 5;
    const int mw   = wid & 7;            // M-warp: rows mw*32..+31
    const int nw   = wid >> 3;           // N-warp: subtile cols nw*32..+31
    const int g      = blockIdx.x;
    const int bchunk = blockIdx.y;
    const int cid    = bchunk * FGROUPS + g;

    // ---- phase 0: exact fp32 target logits (7 rows per CTA) ----
    {
        int ok = 1;
        #pragma unroll
        for (int j = 0; j < 8; j++) ok &= (t32[1 + 2 * (lane + 32 * j)] == 0);
        const int is64 = __all_sync(0xffffffffu, ok);  // int64 targets detected
        if (wid < 7) {
            int row = cid * 7 + wid;
            if (row < BATCH) {
                const int tgt = is64 ? t32[2 * row] : t32[row];
                const float* x = inputs + (size_t)row * NFEAT;
                const float* f = features + (size_t)tgt * NFEAT;
                float sum = 0.f;
                #pragma unroll
                for (int k = lane; k < NFEAT; k += 32) sum = fmaf(x[k], f[k], sum);
                #pragma unroll
                for (int d = 16; d; d >>= 1) sum += __shfl_xor_sync(0xffffffffu, sum, d);
                if (lane == 0) g_tgt[row] = sum * 20.0f;
            }
        }
    }

    // ---- A tile: 256x256 fp32 -> bf16 (prescaled by CSCALE) ----
    {
        const float4* inp4 = (const float4*)(inputs + (size_t)bchunk * BTILE * NFEAT);
        #pragma unroll
        for (int i = 0; i < 32; i++) {
            int idx = tid + i * NTHREADS;
            int row = idx >> 6, c4 = idx & 63;
            float4 v = inp4[idx];
            v.x *= CSCALE; v.y *= CSCALE; v.z *= CSCALE; v.w *= CSCALE;
            *(uint2*)(smem + row * (ASTRIDE * 2) + c4 * 8) = cvt2bf16(v);
        }
    }

    const uint32_t smem_u = (uint32_t)__cvta_generic_to_shared(smem);
    // A: warp owns rows mw*32..+31 (two m16 slabs via mi)
    const int rA = mw * 32 + (lane & 7) + ((lane >> 3) & 1) * 8;
    const int kA = (lane >> 4) * 8;
    const uint32_t aBase = smem_u + (rA * ASTRIDE + kA) * 2;
    // B: warp owns subtile rows nw*32..+31 (four n8 slabs via ni)
    const int rB = nw * 32 + (lane & 7);
    const int kB = (lane >> 3) * 8;
    const uint32_t bOff = (rB * ASTRIDE + kB) * 2;
    const uint32_t bBuf0 = smem_u + A_BYTES;

    float rs[2][2] = {{0.f, 0.f}, {0.f, 0.f}};   // fixed-M partial sums per (mi, h)

    const int s0 = (g * NSUB64) / FGROUPS;
    const int s1 = ((g + 1) * NSUB64) / FGROUPS;

    // prologue: cp.async subtile s0 -> buffer 0 (bf16 bank, pad rows are zero)
    {
        const char* srcb = (const char*)g_featbf + (size_t)s0 * FSUB * NFEAT * 2;
        #pragma unroll
        for (int i = 0; i < 4; i++) {
            int idx = tid + i * NTHREADS;
            int row = idx >> 5, c = idx & 31;
            cpasync16(bBuf0 + row * (ASTRIDE * 2) + c * 16, srcb + row * 512 + c * 16);
        }
        CP_COMMIT();
        CP_WAIT0();
    }

    for (int s = s0; s < s1; s++) {
        const int cur = (s - s0) & 1;
        const bool hn = (s + 1) < s1;
        __syncthreads();   // buf[cur] stores visible to all; prev reads done

        // issue cp.async for B[s+1] into the other buffer (overlaps GEMM+epilogue)
        if (hn) {
            const char* srcb = (const char*)g_featbf + (size_t)(s + 1) * FSUB * NFEAT * 2;
            uint32_t dbase = bBuf0 + (cur ^ 1) * B_BYTES;
            #pragma unroll
            for (int i = 0; i < 4; i++) {
                int idx = tid + i * NTHREADS;
                int row = idx >> 5, c = idx & 31;
                cpasync16(dbase + row * (ASTRIDE * 2) + c * 16, srcb + row * 512 + c * 16);
            }
            CP_COMMIT();
        }

        const uint32_t bb = bBuf0 + cur * B_BYTES + bOff;

        float acc[2][4][4];
        #pragma unroll
        for (int mi = 0; mi < 2; mi++)
            #pragma unroll
            for (int ni = 0; ni < 4; ni++)
                #pragma unroll
                for (int e = 0; e < 4; e++) acc[mi][ni][e] = 0.f;

        #pragma unroll
        for (int kk = 0; kk < 8; kk++) {
            uint32_t a[2][2][4];
            #pragma unroll
            for (int mi = 0; mi < 2; mi++)
                #pragma unroll
                for (int ks = 0; ks < 2; ks++)
                    ldsm4(a[mi][ks][0], a[mi][ks][1], a[mi][ks][2], a[mi][ks][3],
                          aBase + mi * (16 * ASTRIDE * 2) + (kk * 32 + ks * 16) * 2);
            uint32_t b[4][2][2];
            #pragma unroll
            for (int ni = 0; ni < 4; ni++) {
                uint32_t r0, r1, r2, r3;
                ldsm4(r0, r1, r2, r3, bb + ni * (8 * ASTRIDE * 2) + kk * 64);
                b[ni][0][0] = r0; b[ni][0][1] = r1;
                b[ni][1][0] = r2; b[ni][1][1] = r3;
            }
            #pragma unroll
            for (int ks = 0; ks < 2; ks++)
                #pragma unroll
                for (int mi = 0; mi < 2; mi++)
                    #pragma unroll
                    for (int ni = 0; ni < 4; ni++)
                        mma16816(acc[mi][ni], a[mi][ks], b[ni][ks]);
        }

        // ---- fixed-M epilogue: rs[mi][h] += sum_n 2^(v-150) ----
        #pragma unroll
        for (int mi = 0; mi < 2; mi++)
            #pragma unroll
            for (int h = 0; h < 2; h++) {
                float a0 = exp2m150(acc[mi][0][2*h]) + exp2m150(acc[mi][0][2*h+1]);
                float a1 = exp2m150(acc[mi][1][2*h]) + exp2m150(acc[mi][1][2*h+1]);
                float a2 = exp2m150(acc[mi][2][2*h]) + exp2m150(acc[mi][2][2*h+1]);
                float a3 = exp2m150(acc[mi][3][2*h]) + exp2m150(acc[mi][3][2*h+1]);
                rs[mi][h] += (a0 + a1) + (a2 + a3);
            }

        if (hn) CP_WAIT0();   // B[s+1] landed before next iteration's sync
    }

    // combine the 4 lanes owning each row, write partial sums
    #pragma unroll
    for (int mi = 0; mi < 2; mi++)
        #pragma unroll
        for (int h = 0; h < 2; h++) {
            float sv = rs[mi][h];
            sv += __shfl_xor_sync(0xffffffffu, sv, 1);
            sv += __shfl_xor_sync(0xffffffffu, sv, 2);
            if ((lane & 3) == 0) {
                int row = bchunk * BTILE + mw * 32 + mi * 16 + h * 8 + (lane >> 2);
                g_part[(g * 2 + nw) * BATCH + row] = sv;
            }
        }

    // ---- last-CTA final reduction ----
    __syncthreads();
    __threadfence();
    __shared__ int isLast;
    if (tid == 0) isLast = (atomicAdd(&g_sem, 1) == NCTAS - 1);
    __syncthreads();

    if (isLast) {
        __shared__ float red[NTHREADS];
        float nll = 0.f;
        #pragma unroll
        for (int j = 0; j < BATCH / NTHREADS; j++) {
            int b = tid + j * NTHREADS;
            float S = 0.f;
            #pragma unroll 1
            for (int gi = 0; gi < NPART; gi++)
                S += __ldcg(&g_part[gi * BATCH + b]);
            float lse = (FIXM + log2f(S)) * LN2F;
            nll += lse - __ldcg(&g_tgt[b]);
        }
        red[tid] = nll;
        __syncthreads();
        #pragma unroll
        for (int st = NTHREADS / 2; st; st >>= 1) {
            if (tid < st) red[tid] += red[tid + st];
            __syncthreads();
        }
        if (tid == 0) {
            out[0] = red[0] * (1.0f / BATCH);
            g_sem = 0;   // reset for next graph replay
        }
    }
}

// ---------------------------------------------------------------------------
extern "C" void kernel_launch(void* const* d_in, const int* in_sizes, int n_in,
                              void* d_out, int out_size)
{
    const float* inputs   = nullptr;
    const int*   targets  = nullptr;
    const float* features = nullptr;
    for (int i = 0; i < n_in; i++) {
        if (in_sizes[i] == BATCH * NFEAT)      inputs   = (const float*)d_in[i];
        else if (in_sizes[i] == BATCH)         targets  = (const int*)d_in[i];
        else if (in_sizes[i] == NSAMP * NFEAT) features = (const float*)d_in[i];
    }

    cudaFuncSetAttribute(ce_fused, cudaFuncAttributeMaxDynamicSharedMemorySize, SMEM_BYTES);

    cvt_kernel<<<1184, 256>>>(features);
    ce_fused<<<dim3(FGROUPS, BCHUNKS), NTHREADS, SMEM_BYTES>>>(inputs, features, targets,
                                                               (float*)d_out);
}

// round 13
// speedup vs baseline: 1.0211x; 1.0211x over previous
#include <cuda_runtime.h>
#include <cuda_bf16.h>
#include <stdint.h>

// Problem constants
#define BATCH   1024
#define NFEAT   256
#define NSAMP   100000
// Tiling
#define BTILE   256                     // batch rows per CTA
#define NTHREADS 256                    // 8 warps, each m32 x n64
#define FSUB    64                      // feature rows per subtile
#define NSUB64  1563                    // ceil(100000/64)
#define FEATPAD (NSUB64 * FSUB)         // 100032 rows (pad rows zeroed)
#define FGROUPS 37                      // 37 * 4 = 148 CTAs = one wave
#define BCHUNKS (BATCH / BTILE)         // 4
#define NCTAS   (FGROUPS * BCHUNKS)     // 148

#define ASTRIDE 264                     // halves per smem row (+8 pad -> conflict-free ldmatrix)
#define A_BYTES (BTILE * ASTRIDE * 2)   // 135168
#define B_BYTES (FSUB * ASTRIDE * 2)    // 33792
#define SMEM_BYTES (A_BYTES + 2 * B_BYTES)  // 202752 (< 227KB)

#define CSCALE 28.853900817779268f      // (1/0.05) * log2(e): folded into bf16 A
#define LN2F   0.6931471805599453f
#define FIXM   150.0f                   // fixed softmax max (base-2); max logit ~123
#define C1CONST (12582912.0f - 150.0f)  // magic(1.5*2^23) - FIXM

__device__ float g_part[FGROUPS * BATCH];
__device__ float g_tgt[BATCH];
__device__ int   g_sem = 0;
// bf16 feature bank, written once per run by cvt_kernel (pad rows zero)
__device__ __nv_bfloat16 g_featbf[(size_t)FEATPAD * NFEAT];

// 2^(v-150) on the FFMA pipe; clamp v>=24 => exponent >= -126.
__device__ __forceinline__ float exp2m150(float v) {
    v = fmaxf(v, 24.0f);
    float tj = v + C1CONST;
    float fi = tj - C1CONST;
    float f  = v - fi;
    float p  = 0.0096181291f;
    p = fmaf(p, f, 0.0555041087f);
    p = fmaf(p, f, 0.2402265070f);
    p = fmaf(p, f, 0.6931471806f);
    p = fmaf(p, f, 1.0f);
    return __int_as_float(__float_as_int(p) + (__float_as_int(tj) << 23));
}

__device__ __forceinline__ uint2 cvt2bf16(float4 v) {
    __nv_bfloat162 p0, p1;
    p0.x = __float2bfloat16_rn(v.x); p0.y = __float2bfloat16_rn(v.y);
    p1.x = __float2bfloat16_rn(v.z); p1.y = __float2bfloat16_rn(v.w);
    uint2 u;
    u.x = *(uint32_t*)&p0; u.y = *(uint32_t*)&p1;
    return u;
}

__device__ __forceinline__ void ldsm4(uint32_t& r0, uint32_t& r1, uint32_t& r2, uint32_t& r3,
                                      uint32_t addr) {
    asm volatile("ldmatrix.sync.aligned.m8n8.x4.shared.b16 {%0,%1,%2,%3}, [%4];"
                 : "=r"(r0), "=r"(r1), "=r"(r2), "=r"(r3) : "r"(addr));
}

__device__ __forceinline__ void mma16816(float* d, const uint32_t* a, const uint32_t* b) {
    asm volatile("mma.sync.aligned.m16n8k16.row.col.f32.bf16.bf16.f32 "
                 "{%0,%1,%2,%3}, {%4,%5,%6,%7}, {%8,%9}, {%0,%1,%2,%3};"
                 : "+f"(d[0]), "+f"(d[1]), "+f"(d[2]), "+f"(d[3])
                 : "r"(a[0]), "r"(a[1]), "r"(a[2]), "r"(a[3]), "r"(b[0]), "r"(b[1]));
}

__device__ __forceinline__ void cpasync16(uint32_t dst, const void* src) {
    asm volatile("cp.async.cg.shared.global [%0], [%1], 16;" :: "r"(dst), "l"(src) : "memory");
}
#define CP_COMMIT() asm volatile("cp.async.commit_group;" ::: "memory")
#define CP_WAIT0()  asm volatile("cp.async.wait_group 0;" ::: "memory")

// issue cp.async for one 64x256 bf16 subtile (32KB) into a B smem buffer
__device__ __forceinline__ void prefetch_b(uint32_t dst, int s, int tid) {
    const char* srcb = (const char*)g_featbf + (size_t)s * FSUB * NFEAT * 2;
    #pragma unroll
    for (int i = 0; i < 8; i++) {
        int idx = tid + i * NTHREADS;
        int row = idx >> 5, c = idx & 31;
        cpasync16(dst + row * (ASTRIDE * 2) + c * 16, srcb + row * 512 + c * 16);
    }
    CP_COMMIT();
}

// One subtile GEMM into accC, with the exp-epilogue of accP interleaved
// between kk-steps (2 of 16 (mi,ni) groups per kk) when DO_EPI.
template<bool DO_EPI>
__device__ __forceinline__ void gemm_step(float accC[2][8][4], float accP[2][8][4],
                                          float rs[2][2], uint32_t aBase, uint32_t bb)
{
    #pragma unroll
    for (int mi = 0; mi < 2; mi++)
        #pragma unroll
        for (int ni = 0; ni < 8; ni++)
            #pragma unroll
            for (int e = 0; e < 4; e++) accC[mi][ni][e] = 0.f;

    #pragma unroll
    for (int kk = 0; kk < 8; kk++) {
        uint32_t a[2][2][4];
        #pragma unroll
        for (int mi = 0; mi < 2; mi++)
            #pragma unroll
            for (int ks = 0; ks < 2; ks++)
                ldsm4(a[mi][ks][0], a[mi][ks][1], a[mi][ks][2], a[mi][ks][3],
                      aBase + mi * (16 * ASTRIDE * 2) + (kk * 32 + ks * 16) * 2);
        #pragma unroll
        for (int ni = 0; ni < 8; ni++) {
            uint32_t b0, b1, b2, b3;
            ldsm4(b0, b1, b2, b3, bb + ni * (8 * ASTRIDE * 2) + kk * 64);
            uint32_t bk0[2] = {b0, b1};
            uint32_t bk1[2] = {b2, b3};
            mma16816(accC[0][ni], a[0][0], bk0);
            mma16816(accC[1][ni], a[1][0], bk0);
            mma16816(accC[0][ni], a[0][1], bk1);
            mma16816(accC[1][ni], a[1][1], bk1);
        }
        if (DO_EPI) {
            #pragma unroll
            for (int p = 2 * kk; p < 2 * kk + 2; p++) {
                const int mi = p >> 3, ni = p & 7;
                rs[mi][0] += exp2m150(accP[mi][ni][0]) + exp2m150(accP[mi][ni][1]);
                rs[mi][1] += exp2m150(accP[mi][ni][2]) + exp2m150(accP[mi][ni][3]);
            }
        }
    }
}

__device__ __forceinline__ void epi_full(float acc[2][8][4], float rs[2][2]) {
    #pragma unroll
    for (int mi = 0; mi < 2; mi++)
        #pragma unroll
        for (int ni = 0; ni < 8; ni++) {
            rs[mi][0] += exp2m150(acc[mi][ni][0]) + exp2m150(acc[mi][ni][1]);
            rs[mi][1] += exp2m150(acc[mi][ni][2]) + exp2m150(acc[mi][ni][3]);
        }
}

// ---------------------------------------------------------------------------
// Pre-pass: fp32 features -> bf16 bank (pad rows zeroed). Pure streaming.
// ---------------------------------------------------------------------------
__global__ void __launch_bounds__(256)
cvt_kernel(const float* __restrict__ features)
{
    size_t i = (size_t)blockIdx.x * blockDim.x + threadIdx.x;
    const size_t stride = (size_t)gridDim.x * blockDim.x;
    const size_t n_real = (size_t)NSAMP * NFEAT / 8;     // 3,200,000 x 8 floats
    const size_t n_tot  = (size_t)FEATPAD * NFEAT / 8;   // 3,201,024
    const float4* src = (const float4*)features;
    uint4* dst = (uint4*)g_featbf;
    for (; i < n_tot; i += stride) {
        float4 v0, v1;
        if (i < n_real) { v0 = src[2 * i]; v1 = src[2 * i + 1]; }
        else { v0 = make_float4(0.f,0.f,0.f,0.f); v1 = v0; }
        uint2 a = cvt2bf16(v0), b = cvt2bf16(v1);
        dst[i] = make_uint4(a.x, a.y, b.x, b.y);
    }
}

// ---------------------------------------------------------------------------
// Fused main: target dots + pipelined GEMM (256x64 tiles, 8 warps m32n64,
// double accumulators, epi(s) interleaved with GEMM(s+1)) + last-CTA merge.
// ---------------------------------------------------------------------------
__global__ void __launch_bounds__(NTHREADS, 1)
ce_fused(const float* __restrict__ inputs, const float* __restrict__ features,
         const int* __restrict__ t32, float* __restrict__ out)
{
    extern __shared__ char smem[];
    const int tid  = threadIdx.x;
    const int lane = tid & 31;
    const int wid  = tid >> 5;
    const int g      = blockIdx.x;
    const int bchunk = blockIdx.y;
    const int cid    = bchunk * FGROUPS + g;

    // ---- phase 0: exact fp32 target logits (7 rows per CTA) ----
    {
        int ok = 1;
        #pragma unroll
        for (int j = 0; j < 8; j++) ok &= (t32[1 + 2 * (lane + 32 * j)] == 0);
        const int is64 = __all_sync(0xffffffffu, ok);  // int64 targets detected
        if (wid < 7) {
            int row = cid * 7 + wid;
            if (row < BATCH) {
                const int tgt = is64 ? t32[2 * row] : t32[row];
                const float* x = inputs + (size_t)row * NFEAT;
                const float* f = features + (size_t)tgt * NFEAT;
                float sum = 0.f;
                #pragma unroll
                for (int k = lane; k < NFEAT; k += 32) sum = fmaf(x[k], f[k], sum);
                #pragma unroll
                for (int d = 16; d; d >>= 1) sum += __shfl_xor_sync(0xffffffffu, sum, d);
                if (lane == 0) g_tgt[row] = sum * 20.0f;
            }
        }
    }

    // ---- A tile: 256x256 fp32 -> bf16 (prescaled by CSCALE) ----
    {
        const float4* inp4 = (const float4*)(inputs + (size_t)bchunk * BTILE * NFEAT);
        #pragma unroll
        for (int i = 0; i < 64; i++) {
            int idx = tid + i * NTHREADS;
            int row = idx >> 6, c4 = idx & 63;
            float4 v = inp4[idx];
            v.x *= CSCALE; v.y *= CSCALE; v.z *= CSCALE; v.w *= CSCALE;
            *(uint2*)(smem + row * (ASTRIDE * 2) + c4 * 8) = cvt2bf16(v);
        }
    }

    const uint32_t smem_u = (uint32_t)__cvta_generic_to_shared(smem);
    // A: warp owns rows wid*32..+31 (two m16 slabs via mi)
    const int rA = wid * 32 + (lane & 7) + ((lane >> 3) & 1) * 8;
    const int kA = (lane >> 4) * 8;
    const uint32_t aBase = smem_u + (rA * ASTRIDE + kA) * 2;
    // B: every warp reads the full 64-row subtile (eight n8 slabs via ni)
    const int rB = lane & 7;
    const int kB = (lane >> 3) * 8;
    const uint32_t bOff = (rB * ASTRIDE + kB) * 2;
    const uint32_t bBuf0 = smem_u + A_BYTES;

    float rs[2][2] = {{0.f, 0.f}, {0.f, 0.f}};
    float acc0[2][8][4], acc1[2][8][4];

    const int s0 = (g * NSUB64) / FGROUPS;
    const int s1 = ((g + 1) * NSUB64) / FGROUPS;
    const int n  = s1 - s0;                    // 42 or 43 subtiles

    // prologue: B(s0) -> buf0
    prefetch_b(bBuf0, s0, tid);
    CP_WAIT0();

    // subtile 0: GEMM only (no previous epilogue)
    __syncthreads();
    if (1 < n) prefetch_b(bBuf0 + B_BYTES, s0 + 1, tid);
    gemm_step<false>(acc0, acc0, rs, aBase, bBuf0 + bOff);
    CP_WAIT0();

    int i = 1;
    for (; i + 1 < n; i += 2) {
        __syncthreads();
        prefetch_b(bBuf0 + (((i + 1) & 1) ? B_BYTES : 0), s0 + i + 1, tid);
        gemm_step<true>(acc1, acc0, rs, aBase, bBuf0 + ((i & 1) ? B_BYTES : 0) + bOff);
        CP_WAIT0();

        __syncthreads();
        if (i + 2 < n) prefetch_b(bBuf0 + (((i + 2) & 1) ? B_BYTES : 0), s0 + i + 2, tid);
        gemm_step<true>(acc0, acc1, rs, aBase, bBuf0 + (((i + 1) & 1) ? B_BYTES : 0) + bOff);
        CP_WAIT0();
    }
    if (i < n) {   // leftover single subtile (n even)
        __syncthreads();
        gemm_step<true>(acc1, acc0, rs, aBase, bBuf0 + ((i & 1) ? B_BYTES : 0) + bOff);
        epi_full(acc1, rs);
    } else {       // n odd: last GEMM wrote acc0
        epi_full(acc0, rs);
    }

    // combine the 4 lanes owning each row, write partial sums
    #pragma unroll
    for (int mi = 0; mi < 2; mi++)
        #pragma unroll
        for (int h = 0; h < 2; h++) {
            float sv = rs[mi][h];
            sv += __shfl_xor_sync(0xffffffffu, sv, 1);
            sv += __shfl_xor_sync(0xffffffffu, sv, 2);
            if ((lane & 3) == 0) {
                int row = bchunk * BTILE + wid * 32 + mi * 16 + h * 8 + (lane >> 2);
                g_part[g * BATCH + row] = sv;
            }
        }

    // ---- last-CTA final reduction ----
    __syncthreads();
    __threadfence();
    __shared__ int isLast;
    if (tid == 0) isLast = (atomicAdd(&g_sem, 1) == NCTAS - 1);
    __syncthreads();

    if (isLast) {
        __shared__ float red[NTHREADS];
        float nll = 0.f;
        #pragma unroll
        for (int j = 0; j < BATCH / NTHREADS; j++) {
            int b = tid + j * NTHREADS;
            float S = 0.f;
            #pragma unroll 1
            for (int gi = 0; gi < FGROUPS; gi++)
                S += __ldcg(&g_part[gi * BATCH + b]);
            float lse = (FIXM + log2f(S)) * LN2F;
            nll += lse - __ldcg(&g_tgt[b]);
        }
        red[tid] = nll;
        __syncthreads();
        #pragma unroll
        for (int st = NTHREADS / 2; st; st >>= 1) {
            if (tid < st) red[tid] += red[tid + st];
            __syncthreads();
        }
        if (tid == 0) {
            out[0] = red[0] * (1.0f / BATCH);
            g_sem = 0;   // reset for next graph replay
        }
    }
}

// ---------------------------------------------------------------------------
extern "C" void kernel_launch(void* const* d_in, const int* in_sizes, int n_in,
                              void* d_out, int out_size)
{
    const float* inputs   = nullptr;
    const int*   targets  = nullptr;
    const float* features = nullptr;
    for (int i = 0; i < n_in; i++) {
        if (in_sizes[i] == BATCH * NFEAT)      inputs   = (const float*)d_in[i];
        else if (in_sizes[i] == BATCH)         targets  = (const int*)d_in[i];
        else if (in_sizes[i] == NSAMP * NFEAT) features = (const float*)d_in[i];
    }

    cudaFuncSetAttribute(ce_fused, cudaFuncAttributeMaxDynamicSharedMemorySize, SMEM_BYTES);

    cvt_kernel<<<1184, 256>>>(features);
    ce_fused<<<dim3(FGROUPS, BCHUNKS), NTHREADS, SMEM_BYTES>>>(inputs, features, targets,
                                                               (float*)d_out);
}

// round 14
// speedup vs baseline: 1.0314x; 1.0101x over previous
#include <cuda_runtime.h>
#include <cuda_bf16.h>
#include <stdint.h>

// Problem constants
#define BATCH   1024
#define NFEAT   256
#define NSAMP   100000
// Tiling
#define BTILE   256                     // batch rows per CTA
#define NTHREADS 256                    // 8 warps, each m32 x n64; A resident in regs
#define FSUB    64                      // feature rows per subtile
#define NSUB64  1563                    // ceil(100000/64)
#define FEATPAD (NSUB64 * FSUB)         // 100032 rows (pad rows zeroed)
#define FGROUPS 37                      // 37 * 4 = 148 CTAs = one wave
#define BCHUNKS (BATCH / BTILE)         // 4
#define NCTAS   (FGROUPS * BCHUNKS)     // 148

#define ASTRIDE 264                     // halves per smem row (+8 pad -> conflict-free ldmatrix)
#define A_BYTES (BTILE * ASTRIDE * 2)   // 135168
#define B_BYTES (FSUB * ASTRIDE * 2)    // 33792
#define SMEM_BYTES (A_BYTES + 2 * B_BYTES)  // 202752 (< 227KB)

#define CSCALE 28.853900817779268f      // (1/0.05) * log2(e): folded into bf16 A
#define LN2F   0.6931471805599453f
#define FIXM   150.0f                   // fixed softmax max (base-2); max logit ~123
#define C1CONST (12582912.0f - 150.0f)  // magic(1.5*2^23) - FIXM

__device__ float g_part[FGROUPS * BATCH];
__device__ float g_tgt[BATCH];
__device__ int   g_sem = 0;
// bf16 feature bank, written once per run by cvt_kernel (pad rows zero)
__device__ __nv_bfloat16 g_featbf[(size_t)FEATPAD * NFEAT];

// 2^(v-150) on the FFMA pipe; clamp v>=24 => exponent >= -126.
__device__ __forceinline__ float exp2m150(float v) {
    v = fmaxf(v, 24.0f);
    float tj = v + C1CONST;
    float fi = tj - C1CONST;
    float f  = v - fi;
    float p  = 0.0096181291f;
    p = fmaf(p, f, 0.0555041087f);
    p = fmaf(p, f, 0.2402265070f);
    p = fmaf(p, f, 0.6931471806f);
    p = fmaf(p, f, 1.0f);
    return __int_as_float(__float_as_int(p) + (__float_as_int(tj) << 23));
}

__device__ __forceinline__ uint2 cvt2bf16(float4 v) {
    __nv_bfloat162 p0, p1;
    p0.x = __float2bfloat16_rn(v.x); p0.y = __float2bfloat16_rn(v.y);
    p1.x = __float2bfloat16_rn(v.z); p1.y = __float2bfloat16_rn(v.w);
    uint2 u;
    u.x = *(uint32_t*)&p0; u.y = *(uint32_t*)&p1;
    return u;
}

__device__ __forceinline__ void ldsm4(uint32_t& r0, uint32_t& r1, uint32_t& r2, uint32_t& r3,
                                      uint32_t addr) {
    asm volatile("ldmatrix.sync.aligned.m8n8.x4.shared.b16 {%0,%1,%2,%3}, [%4];"
                 : "=r"(r0), "=r"(r1), "=r"(r2), "=r"(r3) : "r"(addr));
}

__device__ __forceinline__ void mma16816(float* d, const uint32_t* a, const uint32_t* b) {
    asm volatile("mma.sync.aligned.m16n8k16.row.col.f32.bf16.bf16.f32 "
                 "{%0,%1,%2,%3}, {%4,%5,%6,%7}, {%8,%9}, {%0,%1,%2,%3};"
                 : "+f"(d[0]), "+f"(d[1]), "+f"(d[2]), "+f"(d[3])
                 : "r"(a[0]), "r"(a[1]), "r"(a[2]), "r"(a[3]), "r"(b[0]), "r"(b[1]));
}

__device__ __forceinline__ void cpasync16(uint32_t dst, const void* src) {
    asm volatile("cp.async.cg.shared.global [%0], [%1], 16;" :: "r"(dst), "l"(src) : "memory");
}
#define CP_COMMIT() asm volatile("cp.async.commit_group;" ::: "memory")
#define CP_WAIT0()  asm volatile("cp.async.wait_group 0;" ::: "memory")

// issue cp.async for one 64x256 bf16 subtile (32KB) into a B smem buffer
__device__ __forceinline__ void prefetch_b(uint32_t dst, int s, int tid) {
    const char* srcb = (const char*)g_featbf + (size_t)s * FSUB * NFEAT * 2;
    #pragma unroll
    for (int i = 0; i < 8; i++) {
        int idx = tid + i * NTHREADS;
        int row = idx >> 5, c = idx & 31;
        cpasync16(dst + row * (ASTRIDE * 2) + c * 16, srcb + row * 512 + c * 16);
    }
    CP_COMMIT();
}

// Half-subtile GEMM (n32: ni NI0..NI0+3) into accC using the register-resident
// A fragments; when EPI, the exp-epilogue of accE (32 floats) is interleaved
// 4 per kk-step so the fma pipe runs under the tensor pipe.
template<int NI0, bool EPI>
__device__ __forceinline__ void gemm_half(float accC[2][4][4], float accE[2][4][4],
                                          float rs[2][2],
                                          const uint32_t (&aR)[2][8][2][4], uint32_t bb)
{
    #pragma unroll
    for (int mi = 0; mi < 2; mi++)
        #pragma unroll
        for (int ni = 0; ni < 4; ni++)
            #pragma unroll
            for (int e = 0; e < 4; e++) accC[mi][ni][e] = 0.f;

    #pragma unroll
    for (int kk = 0; kk < 8; kk++) {
        #pragma unroll
        for (int ni = 0; ni < 4; ni++) {
            uint32_t b0, b1, b2, b3;
            ldsm4(b0, b1, b2, b3, bb + (NI0 + ni) * (8 * ASTRIDE * 2) + kk * 64);
            uint32_t bk0[2] = {b0, b1};
            uint32_t bk1[2] = {b2, b3};
            mma16816(accC[0][ni], aR[0][kk][0], bk0);
            mma16816(accC[1][ni], aR[1][kk][0], bk0);
            mma16816(accC[0][ni], aR[0][kk][1], bk1);
            mma16816(accC[1][ni], aR[1][kk][1], bk1);
        }
        if (EPI) {
            #pragma unroll
            for (int j = 0; j < 4; j++) {
                const int p  = kk * 4 + j;          // 0..31
                const int mi = p >> 4, ni = (p >> 2) & 3, e = p & 3;
                rs[mi][e >> 1] += exp2m150(accE[mi][ni][e]);
            }
        }
    }
}

// ---------------------------------------------------------------------------
// Pre-pass: fp32 features -> bf16 bank (pad rows zeroed). Pure streaming.
// ---------------------------------------------------------------------------
__global__ void __launch_bounds__(256)
cvt_kernel(const float* __restrict__ features)
{
    size_t i = (size_t)blockIdx.x * blockDim.x + threadIdx.x;
    const size_t stride = (size_t)gridDim.x * blockDim.x;
    const size_t n_real = (size_t)NSAMP * NFEAT / 8;
    const size_t n_tot  = (size_t)FEATPAD * NFEAT / 8;
    const float4* src = (const float4*)features;
    uint4* dst = (uint4*)g_featbf;
    for (; i < n_tot; i += stride) {
        float4 v0, v1;
        if (i < n_real) { v0 = src[2 * i]; v1 = src[2 * i + 1]; }
        else { v0 = make_float4(0.f, 0.f, 0.f, 0.f); v1 = v0; }
        uint2 a = cvt2bf16(v0), b = cvt2bf16(v1);
        dst[i] = make_uint4(a.x, a.y, b.x, b.y);
    }
}

// ---------------------------------------------------------------------------
// Fused main: target dots + GEMM with register-resident A (8 warps m32n64,
// half-subtile software pipeline: epi(h) hides under GEMM(h^1)) + merge.
// ---------------------------------------------------------------------------
__global__ void __launch_bounds__(NTHREADS, 1)
ce_fused(const float* __restrict__ inputs, const float* __restrict__ features,
         const int* __restrict__ t32, float* __restrict__ out)
{
    extern __shared__ char smem[];
    const int tid  = threadIdx.x;
    const int lane = tid & 31;
    const int wid  = tid >> 5;
    const int g      = blockIdx.x;
    const int bchunk = blockIdx.y;
    const int cid    = bchunk * FGROUPS + g;

    // ---- phase 0: exact fp32 target logits (7 rows per CTA) ----
    {
        int ok = 1;
        #pragma unroll
        for (int j = 0; j < 8; j++) ok &= (t32[1 + 2 * (lane + 32 * j)] == 0);
        const int is64 = __all_sync(0xffffffffu, ok);  // int64 targets detected
        if (wid < 7) {
            int row = cid * 7 + wid;
            if (row < BATCH) {
                const int tgt = is64 ? t32[2 * row] : t32[row];
                const float* x = inputs + (size_t)row * NFEAT;
                const float* f = features + (size_t)tgt * NFEAT;
                float sum = 0.f;
                #pragma unroll
                for (int k = lane; k < NFEAT; k += 32) sum = fmaf(x[k], f[k], sum);
                #pragma unroll
                for (int d = 16; d; d >>= 1) sum += __shfl_xor_sync(0xffffffffu, sum, d);
                if (lane == 0) g_tgt[row] = sum * 20.0f;
            }
        }
    }

    // ---- A tile: 256x256 fp32 -> bf16 (prescaled by CSCALE) into smem ----
    {
        const float4* inp4 = (const float4*)(inputs + (size_t)bchunk * BTILE * NFEAT);
        #pragma unroll
        for (int i = 0; i < 64; i++) {
            int idx = tid + i * NTHREADS;
            int row = idx >> 6, c4 = idx & 63;
            float4 v = inp4[idx];
            v.x *= CSCALE; v.y *= CSCALE; v.z *= CSCALE; v.w *= CSCALE;
            *(uint2*)(smem + row * (ASTRIDE * 2) + c4 * 8) = cvt2bf16(v);
        }
    }

    const uint32_t smem_u = (uint32_t)__cvta_generic_to_shared(smem);
    const int rA = wid * 32 + (lane & 7) + ((lane >> 3) & 1) * 8;
    const int kA = (lane >> 4) * 8;
    const uint32_t aBase = smem_u + (rA * ASTRIDE + kA) * 2;
    const int rB = lane & 7;
    const int kB = (lane >> 3) * 8;
    const uint32_t bOff = (rB * ASTRIDE + kB) * 2;
    const uint32_t bBuf0 = smem_u + A_BYTES;

    const int s0 = (g * NSUB64) / FGROUPS;
    const int s1 = ((g + 1) * NSUB64) / FGROUPS;

    // start B(s0) while A settles
    prefetch_b(bBuf0, s0, tid);
    __syncthreads();                 // A tile visible to all warps

    // ---- load ALL A fragments into registers (128 regs/thread), once ----
    uint32_t aR[2][8][2][4];
    #pragma unroll
    for (int mi = 0; mi < 2; mi++)
        #pragma unroll
        for (int kk = 0; kk < 8; kk++)
            #pragma unroll
            for (int ks = 0; ks < 2; ks++)
                ldsm4(aR[mi][kk][ks][0], aR[mi][kk][ks][1],
                      aR[mi][kk][ks][2], aR[mi][kk][ks][3],
                      aBase + mi * (16 * ASTRIDE * 2) + (kk * 32 + ks * 16) * 2);

    CP_WAIT0();
    __syncthreads();                 // B(s0) visible to all warps

    float rs[2][2] = {{0.f, 0.f}, {0.f, 0.f}};
    float acc0[2][4][4], acc1[2][4][4];

    // subtile s0: h0 (no pending epi), then h1 hiding epi(h0)
    if (s0 + 1 < s1) prefetch_b(bBuf0 + B_BYTES, s0 + 1, tid);
    gemm_half<0, false>(acc0, acc0, rs, aR, bBuf0 + bOff);
    gemm_half<4, true >(acc1, acc0, rs, aR, bBuf0 + bOff);
    CP_WAIT0();

    for (int s = s0 + 1; s < s1; s++) {
        __syncthreads();             // buf[(s-s0)&1] ready; old reads done
        if (s + 1 < s1)
            prefetch_b(bBuf0 + (((s + 1 - s0) & 1) ? B_BYTES : 0), s + 1, tid);
        const uint32_t bb = bBuf0 + (((s - s0) & 1) ? B_BYTES : 0) + bOff;
        gemm_half<0, true>(acc0, acc1, rs, aR, bb);   // epi of prev subtile h1
        gemm_half<4, true>(acc1, acc0, rs, aR, bb);   // epi of this subtile h0
        CP_WAIT0();
    }

    // drain: epi of the last subtile's h1
    #pragma unroll
    for (int mi = 0; mi < 2; mi++)
        #pragma unroll
        for (int ni = 0; ni < 4; ni++) {
            rs[mi][0] += exp2m150(acc1[mi][ni][0]) + exp2m150(acc1[mi][ni][1]);
            rs[mi][1] += exp2m150(acc1[mi][ni][2]) + exp2m150(acc1[mi][ni][3]);
        }

    // combine the 4 lanes owning each row, write partial sums
    #pragma unroll
    for (int mi = 0; mi < 2; mi++)
        #pragma unroll
        for (int h = 0; h < 2; h++) {
            float sv = rs[mi][h];
            sv += __shfl_xor_sync(0xffffffffu, sv, 1);
            sv += __shfl_xor_sync(0xffffffffu, sv, 2);
            if ((lane & 3) == 0) {
                int row = bchunk * BTILE + wid * 32 + mi * 16 + h * 8 + (lane >> 2);
                g_part[g * BATCH + row] = sv;
            }
        }

    // ---- last-CTA final reduction ----
    __syncthreads();
    __threadfence();
    __shared__ int isLast;
    if (tid == 0) isLast = (atomicAdd(&g_sem, 1) == NCTAS - 1);
    __syncthreads();

    if (isLast) {
        __shared__ float red[NTHREADS];
        float nll = 0.f;
        #pragma unroll
        for (int j = 0; j < BATCH / NTHREADS; j++) {
            int b = tid + j * NTHREADS;
            float S = 0.f;
            #pragma unroll 1
            for (int gi = 0; gi < FGROUPS; gi++)
                S += __ldcg(&g_part[gi * BATCH + b]);
            float lse = (FIXM + log2f(S)) * LN2F;
            nll += lse - __ldcg(&g_tgt[b]);
        }
        red[tid] = nll;
        __syncthreads();
        #pragma unroll
        for (int st = NTHREADS / 2; st; st >>= 1) {
            if (tid < st) red[tid] += red[tid + st];
            __syncthreads();
        }
        if (tid == 0) {
            out[0] = red[0] * (1.0f / BATCH);
            g_sem = 0;   // reset for next graph replay
        }
    }
}

// ---------------------------------------------------------------------------
extern "C" void kernel_launch(void* const* d_in, const int* in_sizes, int n_in,
                              void* d_out, int out_size)
{
    const float* inputs   = nullptr;
    const int*   targets  = nullptr;
    const float* features = nullptr;
    for (int i = 0; i < n_in; i++) {
        if (in_sizes[i] == BATCH * NFEAT)      inputs   = (const float*)d_in[i];
        else if (in_sizes[i] == BATCH)         targets  = (const int*)d_in[i];
        else if (in_sizes[i] == NSAMP * NFEAT) features = (const float*)d_in[i];
    }

    cudaFuncSetAttribute(ce_fused, cudaFuncAttributeMaxDynamicSharedMemorySize, SMEM_BYTES);

    cvt_kernel<<<1184, 256>>>(features);
    ce_fused<<<dim3(FGROUPS, BCHUNKS), NTHREADS, SMEM_BYTES>>>(inputs, features, targets,
                                                               (float*)d_out);
}

// round 16
// speedup vs baseline: 1.0745x; 1.0417x over previous
#include <cuda_runtime.h>
#include <cuda_bf16.h>
#include <stdint.h>

// Problem constants
#define BATCH   1024
#define NFEAT   256
#define NSAMP   100000
// Tiling
#define BTILE   256                     // batch rows per CTA
#define NTHREADS 512                    // 16 warps = 8 (M) x 2 (N), each m32 x n32
#define FSUB    64                      // feature rows per subtile
#define NSUB64  1563                    // ceil(100000/64)
#define FEATPAD (NSUB64 * FSUB)         // 100032 rows (pad rows zeroed)
#define FGROUPS 37                      // 37 * 4 = 148 CTAs = one wave
#define BCHUNKS (BATCH / BTILE)         // 4
#define NCTAS   (FGROUPS * BCHUNKS)     // 148
#define NPART   (FGROUPS * 2)           // 74 partials per batch row (2 N-warps)

#define ASTRIDE 264                     // halves per smem row (+8 pad -> conflict-free ldmatrix)
#define A_BYTES (BTILE * ASTRIDE * 2)   // 135168
#define B_BYTES (FSUB * ASTRIDE * 2)    // 33792
#define SMEM_BYTES (A_BYTES + 2 * B_BYTES)  // 202752 (< 227KB)

#define CSCALE 28.853900817779268f      // (1/0.05) * log2(e): folded into bf16 A
#define LN2F   0.6931471805599453f
#define FIXM   150.0f                   // fixed softmax max (base-2); max logit ~123

__device__ float g_part[NPART * BATCH];
__device__ float g_tgt[BATCH];
__device__ int   g_sem = 0;
// bf16 feature bank, written once per run by cvt_kernel (pad rows zero)
__device__ __nv_bfloat16 g_featbf[(size_t)FEATPAD * NFEAT];

// Hardware exp2 on the (otherwise idle) MUFU pipe. ~2^-22 rel err; underflows to 0.
__device__ __forceinline__ float ex2a(float x) {
    float r;
    asm("ex2.approx.f32 %0, %1;" : "=f"(r) : "f"(x));
    return r;
}

__device__ __forceinline__ uint2 cvt2bf16(float4 v) {
    __nv_bfloat162 p0, p1;
    p0.x = __float2bfloat16_rn(v.x); p0.y = __float2bfloat16_rn(v.y);
    p1.x = __float2bfloat16_rn(v.z); p1.y = __float2bfloat16_rn(v.w);
    uint2 u;
    u.x = *(uint32_t*)&p0; u.y = *(uint32_t*)&p1;
    return u;
}

__device__ __forceinline__ void ldsm4(uint32_t& r0, uint32_t& r1, uint32_t& r2, uint32_t& r3,
                                      uint32_t addr) {
    asm volatile("ldmatrix.sync.aligned.m8n8.x4.shared.b16 {%0,%1,%2,%3}, [%4];"
                 : "=r"(r0), "=r"(r1), "=r"(r2), "=r"(r3) : "r"(addr));
}

__device__ __forceinline__ void mma16816(float* d, const uint32_t* a, const uint32_t* b) {
    asm volatile("mma.sync.aligned.m16n8k16.row.col.f32.bf16.bf16.f32 "
                 "{%0,%1,%2,%3}, {%4,%5,%6,%7}, {%8,%9}, {%0,%1,%2,%3};"
                 : "+f"(d[0]), "+f"(d[1]), "+f"(d[2]), "+f"(d[3])
                 : "r"(a[0]), "r"(a[1]), "r"(a[2]), "r"(a[3]), "r"(b[0]), "r"(b[1]));
}

__device__ __forceinline__ void cpasync16(uint32_t dst, const void* src) {
    asm volatile("cp.async.cg.shared.global [%0], [%1], 16;" :: "r"(dst), "l"(src) : "memory");
}
#define CP_COMMIT() asm volatile("cp.async.commit_group;" ::: "memory")
#define CP_WAIT0()  asm volatile("cp.async.wait_group 0;" ::: "memory")

// ---------------------------------------------------------------------------
// Pre-pass: fp32 features -> bf16 bank (pad rows zeroed). Pure streaming.
// ---------------------------------------------------------------------------
__global__ void __launch_bounds__(256)
cvt_kernel(const float* __restrict__ features)
{
    size_t i = (size_t)blockIdx.x * blockDim.x + threadIdx.x;
    const size_t stride = (size_t)gridDim.x * blockDim.x;
    const size_t n_real = (size_t)NSAMP * NFEAT / 8;
    const size_t n_tot  = (size_t)FEATPAD * NFEAT / 8;
    const float4* src = (const float4*)features;
    uint4* dst = (uint4*)g_featbf;
    for (; i < n_tot; i += stride) {
        float4 v0, v1;
        if (i < n_real) { v0 = src[2 * i]; v1 = src[2 * i + 1]; }
        else { v0 = make_float4(0.f, 0.f, 0.f, 0.f); v1 = v0; }
        uint2 a = cvt2bf16(v0), b = cvt2bf16(v1);
        dst[i] = make_uint4(a.x, a.y, b.x, b.y);
    }
}

// ---------------------------------------------------------------------------
// Fused main: target dots + GEMM (256x64 tiles, 8x2 warps m32n32, cp.async B)
// + MUFU.EX2 epilogue (acc pre-biased by -150) + last-CTA merge.
// ---------------------------------------------------------------------------
__global__ void __launch_bounds__(NTHREADS, 1)
ce_fused(const float* __restrict__ inputs, const float* __restrict__ features,
         const int* __restrict__ t32, float* __restrict__ out)
{
    extern __shared__ char smem[];
    const int tid  = threadIdx.x;
    const int lane = tid & 31;
    const int wid  = tid >> 5;
    const int mw   = wid & 7;            // M-warp: rows mw*32..+31
    const int nw   = wid >> 3;           // N-warp: subtile cols nw*32..+31
    const int g      = blockIdx.x;
    const int bchunk = blockIdx.y;
    const int cid    = bchunk * FGROUPS + g;

    // ---- phase 0: exact fp32 target logits (7 rows per CTA) ----
    {
        int ok = 1;
        #pragma unroll
        for (int j = 0; j < 8; j++) ok &= (t32[1 + 2 * (lane + 32 * j)] == 0);
        const int is64 = __all_sync(0xffffffffu, ok);  // int64 targets detected
        if (wid < 7) {
            int row = cid * 7 + wid;
            if (row < BATCH) {
                const int tgt = is64 ? t32[2 * row] : t32[row];
                const float* x = inputs + (size_t)row * NFEAT;
                const float* f = features + (size_t)tgt * NFEAT;
                float sum = 0.f;
                #pragma unroll
                for (int k = lane; k < NFEAT; k += 32) sum = fmaf(x[k], f[k], sum);
                #pragma unroll
                for (int d = 16; d; d >>= 1) sum += __shfl_xor_sync(0xffffffffu, sum, d);
                if (lane == 0) g_tgt[row] = sum * 20.0f;
            }
        }
    }

    // ---- A tile: 256x256 fp32 -> bf16 (prescaled by CSCALE) ----
    {
        const float4* inp4 = (const float4*)(inputs + (size_t)bchunk * BTILE * NFEAT);
        #pragma unroll
        for (int i = 0; i < 32; i++) {
            int idx = tid + i * NTHREADS;
            int row = idx >> 6, c4 = idx & 63;
            float4 v = inp4[idx];
            v.x *= CSCALE; v.y *= CSCALE; v.z *= CSCALE; v.w *= CSCALE;
            *(uint2*)(smem + row * (ASTRIDE * 2) + c4 * 8) = cvt2bf16(v);
        }
    }

    const uint32_t smem_u = (uint32_t)__cvta_generic_to_shared(smem);
    // A: warp owns rows mw*32..+31 (two m16 slabs via mi)
    const int rA = mw * 32 + (lane & 7) + ((lane >> 3) & 1) * 8;
    const int kA = (lane >> 4) * 8;
    const uint32_t aBase = smem_u + (rA * ASTRIDE + kA) * 2;
    // B: warp owns subtile rows nw*32..+31 (four n8 slabs via ni)
    const int rB = nw * 32 + (lane & 7);
    const int kB = (lane >> 3) * 8;
    const uint32_t bOff = (rB * ASTRIDE + kB) * 2;
    const uint32_t bBuf0 = smem_u + A_BYTES;

    float rs[2][2] = {{0.f, 0.f}, {0.f, 0.f}};   // partial sums of 2^(v-150) per (mi, h)

    const int s0 = (g * NSUB64) / FGROUPS;
    const int s1 = ((g + 1) * NSUB64) / FGROUPS;

    // prologue: cp.async subtile s0 -> buffer 0 (bf16 bank, pad rows are zero)
    {
        const char* srcb = (const char*)g_featbf + (size_t)s0 * FSUB * NFEAT * 2;
        #pragma unroll
        for (int i = 0; i < 4; i++) {
            int idx = tid + i * NTHREADS;
            int row = idx >> 5, c = idx & 31;
            cpasync16(bBuf0 + row * (ASTRIDE * 2) + c * 16, srcb + row * 512 + c * 16);
        }
        CP_COMMIT();
        CP_WAIT0();
    }

    for (int s = s0; s < s1; s++) {
        const int cur = (s - s0) & 1;
        const bool hn = (s + 1) < s1;
        __syncthreads();   // buf[cur] stores visible to all; prev reads done

        // issue cp.async for B[s+1] into the other buffer (overlaps GEMM+epilogue)
        if (hn) {
            const char* srcb = (const char*)g_featbf + (size_t)(s + 1) * FSUB * NFEAT * 2;
            uint32_t dbase = bBuf0 + (cur ^ 1) * B_BYTES;
            #pragma unroll
            for (int i = 0; i < 4; i++) {
                int idx = tid + i * NTHREADS;
                int row = idx >> 5, c = idx & 31;
                cpasync16(dbase + row * (ASTRIDE * 2) + c * 16, srcb + row * 512 + c * 16);
            }
            CP_COMMIT();
        }

        const uint32_t bb = bBuf0 + cur * B_BYTES + bOff;

        // accumulators pre-biased by -FIXM: after K-accumulation acc = logit - 150,
        // so the epilogue is just EX2 + add (underflow -> exact 0 for dead logits).
        float acc[2][4][4];
        #pragma unroll
        for (int mi = 0; mi < 2; mi++)
            #pragma unroll
            for (int ni = 0; ni < 4; ni++)
                #pragma unroll
                for (int e = 0; e < 4; e++) acc[mi][ni][e] = -FIXM;

        #pragma unroll
        for (int kk = 0; kk < 8; kk++) {
            uint32_t a[2][2][4];
            #pragma unroll
            for (int mi = 0; mi < 2; mi++)
                #pragma unroll
                for (int ks = 0; ks < 2; ks++)
                    ldsm4(a[mi][ks][0], a[mi][ks][1], a[mi][ks][2], a[mi][ks][3],
                          aBase + mi * (16 * ASTRIDE * 2) + (kk * 32 + ks * 16) * 2);
            uint32_t b[4][2][2];
            #pragma unroll
            for (int ni = 0; ni < 4; ni++) {
                uint32_t r0, r1, r2, r3;
                ldsm4(r0, r1, r2, r3, bb + ni * (8 * ASTRIDE * 2) + kk * 64);
                b[ni][0][0] = r0; b[ni][0][1] = r1;
                b[ni][1][0] = r2; b[ni][1][1] = r3;
            }
            #pragma unroll
            for (int ks = 0; ks < 2; ks++)
                #pragma unroll
                for (int mi = 0; mi < 2; mi++)
                    #pragma unroll
                    for (int ni = 0; ni < 4; ni++)
                        mma16816(acc[mi][ni], a[mi][ks], b[ni][ks]);
        }

        // ---- epilogue: rs += sum 2^(acc) on the MUFU pipe (2 instr/logit) ----
        #pragma unroll
        for (int mi = 0; mi < 2; mi++)
            #pragma unroll
            for (int h = 0; h < 2; h++) {
                float a0 = ex2a(acc[mi][0][2*h]) + ex2a(acc[mi][0][2*h+1]);
                float a1 = ex2a(acc[mi][1][2*h]) + ex2a(acc[mi][1][2*h+1]);
                float a2 = ex2a(acc[mi][2][2*h]) + ex2a(acc[mi][2][2*h+1]);
                float a3 = ex2a(acc[mi][3][2*h]) + ex2a(acc[mi][3][2*h+1]);
                rs[mi][h] += (a0 + a1) + (a2 + a3);
            }

        if (hn) CP_WAIT0();   // B[s+1] landed before next iteration's sync
    }

    // combine the 4 lanes owning each row, write partial sums
    #pragma unroll
    for (int mi = 0; mi < 2; mi++)
        #pragma unroll
        for (int h = 0; h < 2; h++) {
            float sv = rs[mi][h];
            sv += __shfl_xor_sync(0xffffffffu, sv, 1);
            sv += __shfl_xor_sync(0xffffffffu, sv, 2);
            if ((lane & 3) == 0) {
                int row = bchunk * BTILE + mw * 32 + mi * 16 + h * 8 + (lane >> 2);
                g_part[(g * 2 + nw) * BATCH + row] = sv;
            }
        }

    // ---- last-CTA final reduction ----
    __syncthreads();
    __threadfence();
    __shared__ int isLast;
    if (tid == 0) isLast = (atomicAdd(&g_sem, 1) == NCTAS - 1);
    __syncthreads();

    if (isLast) {
        __shared__ float red[NTHREADS];
        float nll = 0.f;
        #pragma unroll
        for (int j = 0; j < BATCH / NTHREADS; j++) {
            int b = tid + j * NTHREADS;
            float S = 0.f;
            #pragma unroll 1
            for (int gi = 0; gi < NPART; gi++)
                S += __ldcg(&g_part[gi * BATCH + b]);
            float lse = (FIXM + log2f(S)) * LN2F;   // natural-log LSE
            nll += lse - __ldcg(&g_tgt[b]);
        }
        red[tid] = nll;
        __syncthreads();
        #pragma unroll
        for (int st = NTHREADS / 2; st; st >>= 1) {
            if (tid < st) red[tid] += red[tid + st];
            __syncthreads();
        }
        if (tid == 0) {
            out[0] = red[0] * (1.0f / BATCH);
            g_sem = 0;   // reset for next graph replay
        }
    }
}

// ---------------------------------------------------------------------------
extern "C" void kernel_launch(void* const* d_in, const int* in_sizes, int n_in,
                              void* d_out, int out_size)
{
    const float* inputs   = nullptr;
    const int*   targets  = nullptr;
    const float* features = nullptr;
    for (int i = 0; i < n_in; i++) {
        if (in_sizes[i] == BATCH * NFEAT)      inputs   = (const float*)d_in[i];
        else if (in_sizes[i] == BATCH)         targets  = (const int*)d_in[i];
        else if (in_sizes[i] == NSAMP * NFEAT) features = (const float*)d_in[i];
    }

    cudaFuncSetAttribute(ce_fused, cudaFuncAttributeMaxDynamicSharedMemorySize, SMEM_BYTES);

    cvt_kernel<<<1184, 256>>>(features);
    ce_fused<<<dim3(FGROUPS, BCHUNKS), NTHREADS, SMEM_BYTES>>>(inputs, features, targets,
                                                               (float*)d_out);
}